// round 1
// baseline (speedup 1.0000x reference)
#include <cuda_runtime.h>

// LocallyConnected2d: y[b,o,h,w] = sum_{i,kh,kw} x_pad[b,i,h+kh-1,w+kw-1] * W[i,o,h,w,kh,kw] + bias[o,h,w]
// Shapes: x[64,64,32,32] f32, W[64,64,32,32,3,3] f32, bias[64,32,32] f32, y[64,64,32,32] f32.
//
// Round 0: scalar-fp32 FMA-bound baseline.
// Grid: 256 CTAs = 32 h-rows x 4 batch-tiles(16) x 2 cout-tiles(32). 256 threads.
// Thread tile: 8b x 8o x 1w (64 accumulators). Loop over ci (64 iters), staging
// weights (contiguous 288-float rows -> float4) and x rows into smem.

#define CIN   64
#define COUT  64
#define HO    32
#define WO    32
#define BT    16
#define OT    32
#define THREADS 256

__global__ __launch_bounds__(THREADS, 2)
void lc2d_kernel(const float* __restrict__ x,
                 const float* __restrict__ wgt,
                 const float* __restrict__ bias,
                 float* __restrict__ out)
{
    // Ws[o_local][w*9+kk], row padded 288->292 (keeps 16B alignment, compute
    // reads stride 9 across lanes -> conflict-free).
    __shared__ float Ws[OT][292];
    // Xs[kh][col][b_local]: col 0..33 = x cols -1..32 (halo), b-dim padded 16->17
    // so lanes (varying w) hit distinct banks.
    __shared__ float Xs[3][34][17];

    const int tid  = threadIdx.x;
    const int bidx = blockIdx.x;
    const int h    = bidx >> 3;           // 0..31
    const int rem  = bidx & 7;
    const int b0   = (rem >> 1) * BT;     // 0,16,32,48
    const int o0   = (rem & 1) * OT;      // 0,32

    const int wi = tid & 31;              // this thread's w (0..31)
    const int og = (tid >> 5) & 3;        // o-group: 4 groups of 8
    const int bg = tid >> 7;              // b-group: 2 groups of 8

    // Zero Xs once: covers halo cols 0/33 and out-of-bounds h rows for all ci.
    for (int q = tid; q < 3 * 34 * 17; q += THREADS)
        ((float*)Xs)[q] = 0.0f;
    __syncthreads();

    float acc[8][8];
    #pragma unroll
    for (int i = 0; i < 8; i++)
        #pragma unroll
        for (int j = 0; j < 8; j++)
            acc[i][j] = 0.0f;

    for (int ci = 0; ci < CIN; ci++) {
        // ---- stage weights: 32 o-rows x 288 contiguous floats, float4 coalesced ----
        {
            const float* wb = wgt + (size_t)(ci * COUT + o0) * 9216 + h * 288;
            #pragma unroll
            for (int s = 0; s < 9; s++) {
                int q = tid + THREADS * s;         // 0..2303
                int o = q / 72;
                int j = q % 72;
                float4 v = *(const float4*)(wb + (size_t)o * 9216 + 4 * j);
                *(float4*)&Ws[o][4 * j] = v;
            }
        }
        // ---- stage x: 16 b x 3 rows x 32 floats (float4), skip OOB rows (stay zero) ----
        for (int q = tid; q < 384; q += THREADS) {
            int bb = q / 24;
            int r  = q % 24;
            int hh = r >> 3;
            int j4 = r & 7;
            int row = h - 1 + hh;
            if ((unsigned)row < 32u) {
                float4 v = *(const float4*)(x + ((size_t)(b0 + bb) * CIN + ci) * 1024
                                              + row * 32 + 4 * j4);
                int c = 1 + 4 * j4;
                Xs[hh][c + 0][bb] = v.x;
                Xs[hh][c + 1][bb] = v.y;
                Xs[hh][c + 2][bb] = v.z;
                Xs[hh][c + 3][bb] = v.w;
            }
        }
        __syncthreads();

        // ---- compute: 9 taps x (8b x 8o) FMAs ----
        #pragma unroll
        for (int kk = 0; kk < 9; kk++) {
            const int kh = kk / 3;
            const int kw = kk % 3;
            float xv[8];
            #pragma unroll
            for (int bi = 0; bi < 8; bi++)
                xv[bi] = Xs[kh][wi + kw][bg * 8 + bi];
            #pragma unroll
            for (int oi = 0; oi < 8; oi++) {
                float wv = Ws[og * 8 + oi][wi * 9 + kk];
                #pragma unroll
                for (int bi = 0; bi < 8; bi++)
                    acc[bi][oi] = fmaf(xv[bi], wv, acc[bi][oi]);
            }
        }
        __syncthreads();
    }

    // ---- epilogue: add bias, write coalesced over w ----
    #pragma unroll
    for (int oi = 0; oi < 8; oi++) {
        const int o = o0 + og * 8 + oi;
        const float bv = bias[o * (HO * WO) + h * WO + wi];
        #pragma unroll
        for (int bi = 0; bi < 8; bi++) {
            const int b = b0 + bg * 8 + bi;
            out[((size_t)(b * COUT + o) * HO + h) * WO + wi] = acc[bi][oi] + bv;
        }
    }
}

extern "C" void kernel_launch(void* const* d_in, const int* in_sizes, int n_in,
                              void* d_out, int out_size)
{
    const float* x    = (const float*)d_in[0];
    const float* wgt  = (const float*)d_in[1];
    const float* bias = (const float*)d_in[2];
    float* out        = (float*)d_out;

    lc2d_kernel<<<256, THREADS>>>(x, wgt, bias, out);
}